// round 14
// baseline (speedup 1.0000x reference)
#include <cuda_runtime.h>
#include <cuda_bf16.h>
#include <cstdint>

// ---------------------------------------------------------------------------
// BilinearAttention, split-bf16 HMMA + register softmax + sparse gather.
// GEMM: 128x128 tile, BK=32, 4-stage cp.async (load 3 ahead), 1 CTA/SM,
// fragment double-buffering across k-steps (launch_bounds(256,1)).
// Two-chain launcher identical to R13 (776 us proven).
// Output buffer: [ out (B*N*H) | attn (B*N*N) ]
// ---------------------------------------------------------------------------

#define B_   8
#define N_   2048
#define H_   1024

// ------------------------- scratch (no allocations) -------------------------
__device__ __nv_bfloat16 g_Qh[(size_t)B_ * N_ * H_];
__device__ __nv_bfloat16 g_Ql[(size_t)B_ * N_ * H_];
__device__ __nv_bfloat16 g_Wth[(size_t)H_ * H_];
__device__ __nv_bfloat16 g_Wtl[(size_t)H_ * H_];
__device__ __nv_bfloat16 g_Vh[(size_t)B_ * N_ * H_];
__device__ __nv_bfloat16 g_Vl[(size_t)B_ * N_ * H_];
__device__ __nv_bfloat16 g_Ih[(size_t)B_ * N_ * H_];
__device__ __nv_bfloat16 g_Il[(size_t)B_ * N_ * H_];

// ----------------------------- PTX primitives -------------------------------
__device__ __forceinline__ uint32_t smem_u32(const void* p) {
    uint32_t a;
    asm("{ .reg .u64 t; cvta.to.shared.u64 t, %1; cvt.u32.u64 %0, t; }"
        : "=r"(a) : "l"(p));
    return a;
}
__device__ __forceinline__ void cp16(uint32_t dst, const void* src) {
    asm volatile("cp.async.cg.shared.global [%0], [%1], 16;" :: "r"(dst), "l"(src));
}
__device__ __forceinline__ void cp_commit() {
    asm volatile("cp.async.commit_group;" ::: "memory");
}
template<int Nn>
__device__ __forceinline__ void cp_wait() {
    asm volatile("cp.async.wait_group %0;" :: "n"(Nn) : "memory");
}
__device__ __forceinline__ void ldm_x4(uint32_t& r0, uint32_t& r1, uint32_t& r2,
                                       uint32_t& r3, uint32_t addr) {
    asm volatile("ldmatrix.sync.aligned.m8n8.x4.shared.b16 {%0,%1,%2,%3}, [%4];"
                 : "=r"(r0), "=r"(r1), "=r"(r2), "=r"(r3) : "r"(addr));
}
__device__ __forceinline__ void mma16816(float* c, const uint32_t* a, const uint32_t* b) {
    asm volatile(
        "mma.sync.aligned.m16n8k16.row.col.f32.bf16.bf16.f32 "
        "{%0,%1,%2,%3}, {%4,%5,%6,%7}, {%8,%9}, {%0,%1,%2,%3};"
        : "+f"(c[0]), "+f"(c[1]), "+f"(c[2]), "+f"(c[3])
        : "r"(a[0]), "r"(a[1]), "r"(a[2]), "r"(a[3]), "r"(b[0]), "r"(b[1]));
}
__device__ __forceinline__ void stcs_f2(float* p, float2 v) {
    asm volatile("st.global.cs.v2.f32 [%0], {%1, %2};" :: "l"(p), "f"(v.x), "f"(v.y));
}

// ---------------------- split-bf16 tensor-core GEMM --------------------------
// CTA tile 128(M) x 128(N), BK=32. 8 warps, warp tile 32x64.
// Stage 32KB; 4 stages = 128KB; 1 CTA/SM; fragment double-buffering.
#define A_T   8192
#define STAGE (4 * A_T)
#define SMEM_BYTES (4 * STAGE)

template<int EPI>  // 0: split bf16 hi/lo; 1: mask+relu fp32
__global__ __launch_bounds__(256, 1)
void gemm_sp(const __nv_bfloat16* __restrict__ Ah, const __nv_bfloat16* __restrict__ Al,
             const __nv_bfloat16* __restrict__ Bh, const __nv_bfloat16* __restrict__ Bl,
             float* __restrict__ Cf,
             __nv_bfloat16* __restrict__ Ch, __nv_bfloat16* __restrict__ Cl,
             const int* __restrict__ Mask,
             int K, int ldc,
             size_t sA, size_t sB, size_t sC, size_t sM)
{
    extern __shared__ __align__(1024) char smem[];
    const uint32_t sbase = smem_u32(smem);
    const int tid  = threadIdx.x;
    const int wid  = tid >> 5;
    const int lane = tid & 31;
    const int bm = blockIdx.y * 128;
    const int bn = blockIdx.x * 128;
    const int bz = blockIdx.z;

    Ah += (size_t)bz * sA;  Al += (size_t)bz * sA;
    Bh += (size_t)bz * sB;  Bl += (size_t)bz * sB;

    const int warpM = wid >> 1;
    const int warpN = wid & 1;
    const int nc = K >> 5;

    float acc[2][8][4];
#pragma unroll
    for (int i = 0; i < 2; i++)
#pragma unroll
        for (int j = 0; j < 8; j++)
#pragma unroll
            for (int q = 0; q < 4; q++) acc[i][j][q] = 0.f;

    auto load_chunk = [&](int c) {
        const int kk = c << 5;
        const uint32_t st = sbase + (uint32_t)(c & 3) * STAGE;
#pragma unroll
        for (int i = 0; i < 2; ++i) {
            const int s = tid + i * 256;
            const int row = s >> 2, col = s & 3;
            const uint32_t off =
                (uint32_t)row * 64 + ((uint32_t)(col ^ ((row >> 1) & 3)) << 4);
            const size_t ga = (size_t)(bm + row) * K + kk + col * 8;
            const size_t gb = (size_t)(bn + row) * K + kk + col * 8;
            cp16(st + off, Ah + ga);
            cp16(st + A_T + off, Al + ga);
            cp16(st + 2 * A_T + off, Bh + gb);
            cp16(st + 3 * A_T + off, Bl + gb);
        }
        cp_commit();
    };

    const uint32_t aRow = (uint32_t)(warpM * 32 + (lane & 15));
    const uint32_t aKhi = (uint32_t)(lane >> 4);
    const uint32_t bRow = (uint32_t)(warpN * 64 + ((lane & 16) >> 1) + (lane & 7));
    const uint32_t bKhi = (uint32_t)((lane >> 3) & 1);

    // fragment loaders (one k-step = K=16 slice; ks in {0,1} of a BK=32 chunk)
    auto load_frags = [&](uint32_t st, int ks,
                          uint32_t (*ah)[4], uint32_t (*al)[4],
                          uint32_t (*bh)[2], uint32_t (*bl)[2]) {
        const uint32_t sAh = st;
        const uint32_t sAl = st + A_T;
        const uint32_t sBh = st + 2 * A_T;
        const uint32_t sBl = st + 3 * A_T;
#pragma unroll
        for (int mt = 0; mt < 2; ++mt) {
            const uint32_t row = aRow + mt * 16;
            const uint32_t seg = ((uint32_t)(ks * 2) + aKhi) ^ ((row >> 1) & 3);
            const uint32_t off = row * 64 + (seg << 4);
            ldm_x4(ah[mt][0], ah[mt][1], ah[mt][2], ah[mt][3], sAh + off);
            ldm_x4(al[mt][0], al[mt][1], al[mt][2], al[mt][3], sAl + off);
        }
#pragma unroll
        for (int nb = 0; nb < 4; ++nb) {
            const uint32_t row = bRow + nb * 16;
            const uint32_t seg = ((uint32_t)(ks * 2) + bKhi) ^ ((row >> 1) & 3);
            const uint32_t off = row * 64 + (seg << 4);
            ldm_x4(bh[nb * 2][0], bh[nb * 2][1], bh[nb * 2 + 1][0], bh[nb * 2 + 1][1],
                   sBh + off);
            ldm_x4(bl[nb * 2][0], bl[nb * 2][1], bl[nb * 2 + 1][0], bl[nb * 2 + 1][1],
                   sBl + off);
        }
    };

    uint32_t ah[2][2][4], al[2][2][4], bh[2][8][2], bl[2][8][2];

    // prologue: 3 chunks in flight
    load_chunk(0);
    if (nc > 1) load_chunk(1);
    if (nc > 2) load_chunk(2);

    for (int c = 0; c < nc; ++c) {
        if (c + 2 < nc)      cp_wait<2>();
        else if (c + 1 < nc) cp_wait<1>();
        else                 cp_wait<0>();
        __syncthreads();
        if (c + 3 < nc) load_chunk(c + 3);

        const uint32_t st = sbase + (uint32_t)(c & 3) * STAGE;
        load_frags(st, 0, ah[0], al[0], bh[0], bl[0]);
#pragma unroll
        for (int ks = 0; ks < 2; ++ks) {
            // pass 1: Ah*Bh
#pragma unroll
            for (int mt = 0; mt < 2; ++mt)
#pragma unroll
                for (int nt = 0; nt < 8; ++nt)
                    mma16816(acc[mt][nt], ah[ks][mt], bh[ks][nt]);
            // prefetch next k-step's fragments behind the MMA passes
            if (ks == 0)
                load_frags(st, 1, ah[1], al[1], bh[1], bl[1]);
            // pass 2: Al*Bh
#pragma unroll
            for (int mt = 0; mt < 2; ++mt)
#pragma unroll
                for (int nt = 0; nt < 8; ++nt)
                    mma16816(acc[mt][nt], al[ks][mt], bh[ks][nt]);
            // pass 3: Ah*Bl
#pragma unroll
            for (int mt = 0; mt < 2; ++mt)
#pragma unroll
                for (int nt = 0; nt < 8; ++nt)
                    mma16816(acc[mt][nt], ah[ks][mt], bl[ks][nt]);
        }
    }

    // ------------------------------ epilogue --------------------------------
    const int rBase = bm + warpM * 32 + (lane >> 2);
    const int cBase = bn + warpN * 64 + (lane & 3) * 2;
#pragma unroll
    for (int mt = 0; mt < 2; ++mt) {
#pragma unroll
        for (int half = 0; half < 2; ++half) {
            const int row = rBase + mt * 16 + half * 8;
#pragma unroll
            for (int nt = 0; nt < 8; ++nt) {
                const int col = cBase + nt * 8;
                const float v0 = acc[mt][nt][half * 2 + 0];
                const float v1 = acc[mt][nt][half * 2 + 1];
                if (EPI == 0) {
                    __nv_bfloat16 hv[2], lv[2];
                    hv[0] = __float2bfloat16(v0);
                    lv[0] = __float2bfloat16(v0 - __bfloat162float(hv[0]));
                    hv[1] = __float2bfloat16(v1);
                    lv[1] = __float2bfloat16(v1 - __bfloat162float(hv[1]));
                    *reinterpret_cast<uint32_t*>(Ch + (size_t)row * ldc + col) =
                        *reinterpret_cast<const uint32_t*>(hv);
                    *reinterpret_cast<uint32_t*>(Cl + (size_t)row * ldc + col) =
                        *reinterpret_cast<const uint32_t*>(lv);
                } else {
                    const int2 m = *reinterpret_cast<const int2*>(
                        Mask + (size_t)bz * sM + (size_t)row * ldc + col);
                    float2 v;
                    v.x = m.x > 0 ? fmaxf(v0, 0.f) : -1e9f;
                    v.y = m.y > 0 ? fmaxf(v1, 0.f) : -1e9f;
                    stcs_f2(Cf + (size_t)bz * sC + (size_t)row * ldc + col, v);
                }
            }
        }
    }
}

// --------------------------- conversion kernels -----------------------------
__global__ __launch_bounds__(256)
void split_kernel(const float* __restrict__ x, __nv_bfloat16* __restrict__ h,
                  __nv_bfloat16* __restrict__ l, size_t n)
{
    const size_t i = ((size_t)blockIdx.x * blockDim.x + threadIdx.x) * 4;
    if (i >= n) return;
    const float4 v = *reinterpret_cast<const float4*>(x + i);
    __nv_bfloat16 hv[4], lv[4];
    const float vv[4] = {v.x, v.y, v.z, v.w};
#pragma unroll
    for (int j = 0; j < 4; ++j) {
        const __nv_bfloat16 hh = __float2bfloat16(vv[j]);
        hv[j] = hh;
        lv[j] = __float2bfloat16(vv[j] - __bfloat162float(hh));
    }
    *reinterpret_cast<uint2*>(h + i) = *reinterpret_cast<const uint2*>(hv);
    *reinterpret_cast<uint2*>(l + i) = *reinterpret_cast<const uint2*>(lv);
}

// Transpose+split: in [R,C] -> ht/lt [C,R]
__global__ __launch_bounds__(256)
void tsplit_kernel(const float* __restrict__ x,
                   __nv_bfloat16* __restrict__ ht, __nv_bfloat16* __restrict__ lt,
                   int R, int C)
{
    __shared__ float t[64][65];
    const int r0 = blockIdx.y * 64, c0 = blockIdx.x * 64;
    const int tid = threadIdx.x;

    const int rr = tid >> 4;
    const int cc = (tid & 15) * 4;
#pragma unroll
    for (int i = 0; i < 4; ++i) {
        const int row = rr + i * 16;
        const float4 v = *reinterpret_cast<const float4*>(
            x + (size_t)(r0 + row) * C + c0 + cc);
        t[row][cc] = v.x; t[row][cc + 1] = v.y;
        t[row][cc + 2] = v.z; t[row][cc + 3] = v.w;
    }
    __syncthreads();

#pragma unroll
    for (int i = 0; i < 2; ++i) {
        const int s = tid + i * 256;
        const int orow = s >> 3;
        const int oc = (s & 7) * 8;
        __nv_bfloat16 hv[8], lv[8];
#pragma unroll
        for (int j = 0; j < 8; ++j) {
            const float v = t[oc + j][orow];
            hv[j] = __float2bfloat16(v);
            lv[j] = __float2bfloat16(v - __bfloat162float(hv[j]));
        }
        const size_t o = (size_t)(c0 + orow) * R + r0 + oc;
        *reinterpret_cast<uint4*>(ht + o) = *reinterpret_cast<const uint4*>(hv);
        *reinterpret_cast<uint4*>(lt + o) = *reinterpret_cast<const uint4*>(lv);
    }
}

// ------------------ fused softmax + sparse-gather output --------------------
#define SIG_CAP 512
__global__ __launch_bounds__(256)
void softmax_out_kernel(float* __restrict__ attn, const float* __restrict__ V,
                        float* __restrict__ out)
{
    const int rowg = blockIdx.x;           // 0 .. (slabBatches*N)-1
    const int bz   = rowg >> 11;           // / N_
    float* p = attn + (size_t)rowg * N_;
    const float* Vb = V + (size_t)bz * N_ * H_;
    const int tid = threadIdx.x;

    __shared__ float red[256];
    __shared__ int   idxs[SIG_CAP];
    __shared__ float wts[SIG_CAP];
    __shared__ int   cnt;
    if (tid == 0) cnt = 0;

    float x[8];
#pragma unroll
    for (int j = 0; j < 8; ++j) x[j] = p[tid + j * 256];

    float lmax = x[0];
#pragma unroll
    for (int j = 1; j < 8; ++j) lmax = fmaxf(lmax, x[j]);
    red[tid] = lmax;
    __syncthreads();
#pragma unroll
    for (int s = 128; s > 0; s >>= 1) {
        if (tid < s) red[tid] = fmaxf(red[tid], red[tid + s]);
        __syncthreads();
    }
    const float rmax = red[0];
    __syncthreads();

    float lsum = 0.f;
#pragma unroll
    for (int j = 0; j < 8; ++j) {
        x[j] = __expf(x[j] - rmax);
        lsum += x[j];
    }
    red[tid] = lsum;
    __syncthreads();
#pragma unroll
    for (int s = 128; s > 0; s >>= 1) {
        if (tid < s) red[tid] += red[tid + s];
        __syncthreads();
    }
    const float inv = 1.0f / red[0];
    __syncthreads();

#pragma unroll
    for (int j = 0; j < 8; ++j) {
        const float w = x[j] * inv;
        x[j] = w;
        p[tid + j * 256] = w;
        if (w > 1e-9f) {
            const int s = atomicAdd(&cnt, 1);
            if (s < SIG_CAP) { idxs[s] = tid + j * 256; wts[s] = w; }
        }
    }
    __syncthreads();

    const int n = cnt;
    if (tid == 0 && n > 1 && n <= SIG_CAP) {
        for (int i = 1; i < n; ++i) {
            const int ki = idxs[i]; const float kw = wts[i];
            int j = i - 1;
            while (j >= 0 && idxs[j] > ki) {
                idxs[j + 1] = idxs[j]; wts[j + 1] = wts[j]; --j;
            }
            idxs[j + 1] = ki; wts[j + 1] = kw;
        }
    }
    __syncthreads();

    const int col = tid * 4;
    float4 acc = make_float4(0.f, 0.f, 0.f, 0.f);
    if (n <= SIG_CAP) {
        for (int s = 0; s < n; ++s) {
            const float w = wts[s];
            const float4 v = *reinterpret_cast<const float4*>(
                Vb + (size_t)idxs[s] * H_ + col);
            acc.x += w * v.x; acc.y += w * v.y;
            acc.z += w * v.z; acc.w += w * v.w;
        }
    } else {
        for (int i = 0; i < N_; ++i) {
            const float w = p[i];
            if (w > 0.f) {
                const float4 v = *reinterpret_cast<const float4*>(
                    Vb + (size_t)i * H_ + col);
                acc.x += w * v.x; acc.y += w * v.y;
                acc.z += w * v.z; acc.w += w * v.w;
            }
        }
    }
    *reinterpret_cast<float4*>(out + (size_t)rowg * H_ + col) = acc;
}

// --------------------------------- launch -----------------------------------
extern "C" void kernel_launch(void* const* d_in, const int* in_sizes, int n_in,
                              void* d_out, int out_size)
{
    const float* query = (const float*)d_in[0];   // (B, N, H)
    const float* value = (const float*)d_in[1];   // (B, N, H)
    const int*   mask  = (const int*)d_in[2];     // (B, N, N)
    const float* W     = (const float*)d_in[3];   // (H, H)

    float* out  = (float*)d_out;                   // (B, N, H)
    float* attn = out + (size_t)B_ * N_ * H_;      // (B, N, N)

    __nv_bfloat16 *Qh, *Ql, *Wth, *Wtl, *Vh, *Vl, *Ih, *Il;
    cudaGetSymbolAddress((void**)&Qh,  g_Qh);
    cudaGetSymbolAddress((void**)&Ql,  g_Ql);
    cudaGetSymbolAddress((void**)&Wth, g_Wth);
    cudaGetSymbolAddress((void**)&Wtl, g_Wtl);
    cudaGetSymbolAddress((void**)&Vh,  g_Vh);
    cudaGetSymbolAddress((void**)&Vl,  g_Vl);
    cudaGetSymbolAddress((void**)&Ih,  g_Ih);
    cudaGetSymbolAddress((void**)&Il,  g_Il);

    cudaFuncSetAttribute(gemm_sp<0>, cudaFuncAttributeMaxDynamicSharedMemorySize, SMEM_BYTES);
    cudaFuncSetAttribute(gemm_sp<1>, cudaFuncAttributeMaxDynamicSharedMemorySize, SMEM_BYTES);

    // one side stream + two re-recorded events (proven allocation footprint)
    static cudaStream_t s2 = nullptr;
    static cudaEvent_t evA = nullptr, evB = nullptr;
    if (!s2) {
        cudaStreamCreateWithFlags(&s2, cudaStreamNonBlocking);
        cudaEventCreateWithFlags(&evA, cudaEventDisableTiming);
        cudaEventCreateWithFlags(&evB, cudaEventDisableTiming);
    }

    const size_t nQ  = (size_t)B_ * N_ * H_;
    const size_t bQ  = (size_t)N_ * H_;       // per-batch Q/V/interm elems
    const size_t bAt = (size_t)N_ * N_;       // per-batch attn/mask elems
    const int    HB  = B_ / 2;                // batches per chain
    const size_t oQ  = (size_t)HB * bQ;       // chain-B offsets
    const size_t oAt = (size_t)HB * bAt;

    // 1) fork
    cudaEventRecord(evA, 0);
    cudaStreamWaitEvent(s2, evA, 0);

    // 2) s2: V split; evB = "V ready"
    split_kernel<<<(unsigned)(nQ / 4 / 256), 256, 0, s2>>>(value, Vh, Vl, nQ);
    cudaEventRecord(evB, s2);

    // 3) default: Q split + W transpose; evA (re-record) = "Q/W ready"
    split_kernel<<<(unsigned)(nQ / 4 / 256), 256>>>(query, Qh, Ql, nQ);
    tsplit_kernel<<<dim3(H_ / 64, H_ / 64), 256>>>(W, Wth, Wtl, H_, H_);
    cudaEventRecord(evA, 0);
    cudaStreamWaitEvent(s2, evA, 0);

    // 4) chain A on default: GEMM1(0-3); wait V; GEMM2(0-3); softmax(0-3)
    gemm_sp<0><<<dim3(H_ / 128, (HB * N_) / 128, 1), 256, SMEM_BYTES>>>(
        Qh, Ql, Wth, Wtl, nullptr, Ih, Il, nullptr,
        H_, H_, 0, 0, 0, 0);
    cudaStreamWaitEvent(0, evB, 0);   // V ready (binds to record in step 2)
    gemm_sp<1><<<dim3(N_ / 128, N_ / 128, HB), 256, SMEM_BYTES>>>(
        Ih, Il, Vh, Vl, attn, nullptr, nullptr, mask,
        H_, N_, bQ, bQ, bAt, bAt);
    softmax_out_kernel<<<HB * N_, 256>>>(attn, value, out);

    // 5) chain B on s2: GEMM1(4-7); GEMM2(4-7)
    gemm_sp<0><<<dim3(H_ / 128, (HB * N_) / 128, 1), 256, SMEM_BYTES, s2>>>(
        Qh + oQ, Ql + oQ, Wth, Wtl, nullptr, Ih + oQ, Il + oQ, nullptr,
        H_, H_, 0, 0, 0, 0);
    gemm_sp<1><<<dim3(N_ / 128, N_ / 128, HB), 256, SMEM_BYTES, s2>>>(
        Ih + oQ, Il + oQ, Vh + oQ, Vl + oQ, attn + oAt, nullptr, nullptr,
        mask + oAt, H_, N_, bQ, bQ, bAt, bAt);

    // 6) tail split: chain-B softmax runs half on each stream.
    cudaEventRecord(evA, s2);
    cudaStreamWaitEvent(0, evA, 0);
    const int HHB = HB / 2;
    softmax_out_kernel<<<HHB * N_, 256>>>(
        attn + oAt, value + oQ, out + oQ);
    softmax_out_kernel<<<HHB * N_, 256, 0, s2>>>(
        attn + oAt + (size_t)HHB * bAt,
        value + oQ + (size_t)HHB * bQ,
        out + oQ + (size_t)HHB * bQ);

    // 7) join
    cudaEventRecord(evB, s2);
    cudaStreamWaitEvent(0, evB, 0);
}

// round 15
// speedup vs baseline: 1.1750x; 1.1750x over previous
#include <cuda_runtime.h>
#include <cuda_bf16.h>
#include <cstdint>

// ---------------------------------------------------------------------------
// BilinearAttention, split-bf16 HMMA + register softmax + sparse gather.
// Two-chain batch pipeline (A: batches 0-3 on stream 0, B: 4-7 on s2).
// R13 kernels verbatim; launcher delta: per-chain Q splits so chain A's
// GEMM1 starts after W + Q[0-3] only. 1 stream + 2 re-recorded events.
// Output buffer: [ out (B*N*H) | attn (B*N*N) ]
// ---------------------------------------------------------------------------

#define B_   8
#define N_   2048
#define H_   1024

// ------------------------- scratch (no allocations) -------------------------
__device__ __nv_bfloat16 g_Qh[(size_t)B_ * N_ * H_];
__device__ __nv_bfloat16 g_Ql[(size_t)B_ * N_ * H_];
__device__ __nv_bfloat16 g_Wth[(size_t)H_ * H_];
__device__ __nv_bfloat16 g_Wtl[(size_t)H_ * H_];
__device__ __nv_bfloat16 g_Vh[(size_t)B_ * N_ * H_];
__device__ __nv_bfloat16 g_Vl[(size_t)B_ * N_ * H_];
__device__ __nv_bfloat16 g_Ih[(size_t)B_ * N_ * H_];
__device__ __nv_bfloat16 g_Il[(size_t)B_ * N_ * H_];

// ----------------------------- PTX primitives -------------------------------
__device__ __forceinline__ uint32_t smem_u32(const void* p) {
    uint32_t a;
    asm("{ .reg .u64 t; cvta.to.shared.u64 t, %1; cvt.u32.u64 %0, t; }"
        : "=r"(a) : "l"(p));
    return a;
}
__device__ __forceinline__ void cp16(uint32_t dst, const void* src) {
    asm volatile("cp.async.cg.shared.global [%0], [%1], 16;" :: "r"(dst), "l"(src));
}
__device__ __forceinline__ void cp_commit() {
    asm volatile("cp.async.commit_group;" ::: "memory");
}
template<int Nn>
__device__ __forceinline__ void cp_wait() {
    asm volatile("cp.async.wait_group %0;" :: "n"(Nn) : "memory");
}
__device__ __forceinline__ void ldm_x4(uint32_t& r0, uint32_t& r1, uint32_t& r2,
                                       uint32_t& r3, uint32_t addr) {
    asm volatile("ldmatrix.sync.aligned.m8n8.x4.shared.b16 {%0,%1,%2,%3}, [%4];"
                 : "=r"(r0), "=r"(r1), "=r"(r2), "=r"(r3) : "r"(addr));
}
__device__ __forceinline__ void mma16816(float* c, const uint32_t* a, const uint32_t* b) {
    asm volatile(
        "mma.sync.aligned.m16n8k16.row.col.f32.bf16.bf16.f32 "
        "{%0,%1,%2,%3}, {%4,%5,%6,%7}, {%8,%9}, {%0,%1,%2,%3};"
        : "+f"(c[0]), "+f"(c[1]), "+f"(c[2]), "+f"(c[3])
        : "r"(a[0]), "r"(a[1]), "r"(a[2]), "r"(a[3]), "r"(b[0]), "r"(b[1]));
}
__device__ __forceinline__ void stcs_f2(float* p, float2 v) {
    asm volatile("st.global.cs.v2.f32 [%0], {%1, %2};" :: "l"(p), "f"(v.x), "f"(v.y));
}

// ---------------------- split-bf16 tensor-core GEMM --------------------------
// CTA tile 128(M) x 128(N), BK=32. 8 warps, warp tile 32x64.
// Stage 32KB; 3 stages = 96KB; 2 CTAs/SM. (R13-proven)
#define A_T   8192
#define STAGE (4 * A_T)
#define SMEM_BYTES (3 * STAGE)

template<int EPI>  // 0: split bf16 hi/lo; 1: mask+relu fp32
__global__ __launch_bounds__(256, 2)
void gemm_sp(const __nv_bfloat16* __restrict__ Ah, const __nv_bfloat16* __restrict__ Al,
             const __nv_bfloat16* __restrict__ Bh, const __nv_bfloat16* __restrict__ Bl,
             float* __restrict__ Cf,
             __nv_bfloat16* __restrict__ Ch, __nv_bfloat16* __restrict__ Cl,
             const int* __restrict__ Mask,
             int K, int ldc,
             size_t sA, size_t sB, size_t sC, size_t sM)
{
    extern __shared__ __align__(1024) char smem[];
    const uint32_t sbase = smem_u32(smem);
    const int tid  = threadIdx.x;
    const int wid  = tid >> 5;
    const int lane = tid & 31;
    const int bm = blockIdx.y * 128;
    const int bn = blockIdx.x * 128;
    const int bz = blockIdx.z;

    Ah += (size_t)bz * sA;  Al += (size_t)bz * sA;
    Bh += (size_t)bz * sB;  Bl += (size_t)bz * sB;

    const int warpM = wid >> 1;
    const int warpN = wid & 1;
    const int nc = K >> 5;

    float acc[2][8][4];
#pragma unroll
    for (int i = 0; i < 2; i++)
#pragma unroll
        for (int j = 0; j < 8; j++)
#pragma unroll
            for (int q = 0; q < 4; q++) acc[i][j][q] = 0.f;

    auto load_chunk = [&](int c) {
        const int kk = c << 5;
        const uint32_t st = sbase + (uint32_t)(c % 3) * STAGE;
#pragma unroll
        for (int i = 0; i < 2; ++i) {
            const int s = tid + i * 256;
            const int row = s >> 2, col = s & 3;
            const uint32_t off =
                (uint32_t)row * 64 + ((uint32_t)(col ^ ((row >> 1) & 3)) << 4);
            const size_t ga = (size_t)(bm + row) * K + kk + col * 8;
            const size_t gb = (size_t)(bn + row) * K + kk + col * 8;
            cp16(st + off, Ah + ga);
            cp16(st + A_T + off, Al + ga);
            cp16(st + 2 * A_T + off, Bh + gb);
            cp16(st + 3 * A_T + off, Bl + gb);
        }
        cp_commit();
    };

    const uint32_t aRow = (uint32_t)(warpM * 32 + (lane & 15));
    const uint32_t aKhi = (uint32_t)(lane >> 4);
    const uint32_t bRow = (uint32_t)(warpN * 64 + ((lane & 16) >> 1) + (lane & 7));
    const uint32_t bKhi = (uint32_t)((lane >> 3) & 1);

    auto compute_chunk = [&](int buf) {
        const uint32_t st  = sbase + (uint32_t)buf * STAGE;
        const uint32_t sAh = st;
        const uint32_t sAl = st + A_T;
        const uint32_t sBh = st + 2 * A_T;
        const uint32_t sBl = st + 3 * A_T;
#pragma unroll
        for (int ks = 0; ks < 2; ++ks) {
            uint32_t ah[2][4], al[2][4], bh[8][2], bl[8][2];
#pragma unroll
            for (int mt = 0; mt < 2; ++mt) {
                const uint32_t row = aRow + mt * 16;
                const uint32_t seg = ((uint32_t)(ks * 2) + aKhi) ^ ((row >> 1) & 3);
                const uint32_t off = row * 64 + (seg << 4);
                ldm_x4(ah[mt][0], ah[mt][1], ah[mt][2], ah[mt][3], sAh + off);
                ldm_x4(al[mt][0], al[mt][1], al[mt][2], al[mt][3], sAl + off);
            }
#pragma unroll
            for (int nb = 0; nb < 4; ++nb) {
                const uint32_t row = bRow + nb * 16;
                const uint32_t seg = ((uint32_t)(ks * 2) + bKhi) ^ ((row >> 1) & 3);
                ldm_x4(bh[nb * 2][0], bh[nb * 2][1], bh[nb * 2 + 1][0], bh[nb * 2 + 1][1],
                       sBh + row * 64 + (seg << 4));
            }
            // Bl into separate registers: overlaps the next two MMA passes
#pragma unroll
            for (int nb = 0; nb < 4; ++nb) {
                const uint32_t row = bRow + nb * 16;
                const uint32_t seg = ((uint32_t)(ks * 2) + bKhi) ^ ((row >> 1) & 3);
                ldm_x4(bl[nb * 2][0], bl[nb * 2][1], bl[nb * 2 + 1][0], bl[nb * 2 + 1][1],
                       sBl + row * 64 + (seg << 4));
            }
#pragma unroll
            for (int mt = 0; mt < 2; ++mt)
#pragma unroll
                for (int nt = 0; nt < 8; ++nt)
                    mma16816(acc[mt][nt], ah[mt], bh[nt]);   // Ah*Bh
#pragma unroll
            for (int mt = 0; mt < 2; ++mt)
#pragma unroll
                for (int nt = 0; nt < 8; ++nt)
                    mma16816(acc[mt][nt], al[mt], bh[nt]);   // Al*Bh
#pragma unroll
            for (int mt = 0; mt < 2; ++mt)
#pragma unroll
                for (int nt = 0; nt < 8; ++nt)
                    mma16816(acc[mt][nt], ah[mt], bl[nt]);   // Ah*Bl
        }
    };

    load_chunk(0);
    load_chunk(1);
    for (int c = 0; c < nc; ++c) {
        if (c + 1 < nc) cp_wait<1>(); else cp_wait<0>();
        __syncthreads();
        if (c + 2 < nc) load_chunk(c + 2);
        compute_chunk(c % 3);
    }

    // ------------------------------ epilogue --------------------------------
    const int rBase = bm + warpM * 32 + (lane >> 2);
    const int cBase = bn + warpN * 64 + (lane & 3) * 2;
#pragma unroll
    for (int mt = 0; mt < 2; ++mt) {
#pragma unroll
        for (int half = 0; half < 2; ++half) {
            const int row = rBase + mt * 16 + half * 8;
#pragma unroll
            for (int nt = 0; nt < 8; ++nt) {
                const int col = cBase + nt * 8;
                const float v0 = acc[mt][nt][half * 2 + 0];
                const float v1 = acc[mt][nt][half * 2 + 1];
                if (EPI == 0) {
                    __nv_bfloat16 hv[2], lv[2];
                    hv[0] = __float2bfloat16(v0);
                    lv[0] = __float2bfloat16(v0 - __bfloat162float(hv[0]));
                    hv[1] = __float2bfloat16(v1);
                    lv[1] = __float2bfloat16(v1 - __bfloat162float(hv[1]));
                    *reinterpret_cast<uint32_t*>(Ch + (size_t)row * ldc + col) =
                        *reinterpret_cast<const uint32_t*>(hv);
                    *reinterpret_cast<uint32_t*>(Cl + (size_t)row * ldc + col) =
                        *reinterpret_cast<const uint32_t*>(lv);
                } else {
                    const int2 m = *reinterpret_cast<const int2*>(
                        Mask + (size_t)bz * sM + (size_t)row * ldc + col);
                    float2 v;
                    v.x = m.x > 0 ? fmaxf(v0, 0.f) : -1e9f;
                    v.y = m.y > 0 ? fmaxf(v1, 0.f) : -1e9f;
                    stcs_f2(Cf + (size_t)bz * sC + (size_t)row * ldc + col, v);
                }
            }
        }
    }
}

// --------------------------- conversion kernels -----------------------------
__global__ __launch_bounds__(256)
void split_kernel(const float* __restrict__ x, __nv_bfloat16* __restrict__ h,
                  __nv_bfloat16* __restrict__ l, size_t n)
{
    const size_t i = ((size_t)blockIdx.x * blockDim.x + threadIdx.x) * 4;
    if (i >= n) return;
    const float4 v = *reinterpret_cast<const float4*>(x + i);
    __nv_bfloat16 hv[4], lv[4];
    const float vv[4] = {v.x, v.y, v.z, v.w};
#pragma unroll
    for (int j = 0; j < 4; ++j) {
        const __nv_bfloat16 hh = __float2bfloat16(vv[j]);
        hv[j] = hh;
        lv[j] = __float2bfloat16(vv[j] - __bfloat162float(hh));
    }
    *reinterpret_cast<uint2*>(h + i) = *reinterpret_cast<const uint2*>(hv);
    *reinterpret_cast<uint2*>(l + i) = *reinterpret_cast<const uint2*>(lv);
}

// Transpose+split: in [R,C] -> ht/lt [C,R]
__global__ __launch_bounds__(256)
void tsplit_kernel(const float* __restrict__ x,
                   __nv_bfloat16* __restrict__ ht, __nv_bfloat16* __restrict__ lt,
                   int R, int C)
{
    __shared__ float t[64][65];
    const int r0 = blockIdx.y * 64, c0 = blockIdx.x * 64;
    const int tid = threadIdx.x;

    const int rr = tid >> 4;
    const int cc = (tid & 15) * 4;
#pragma unroll
    for (int i = 0; i < 4; ++i) {
        const int row = rr + i * 16;
        const float4 v = *reinterpret_cast<const float4*>(
            x + (size_t)(r0 + row) * C + c0 + cc);
        t[row][cc] = v.x; t[row][cc + 1] = v.y;
        t[row][cc + 2] = v.z; t[row][cc + 3] = v.w;
    }
    __syncthreads();

#pragma unroll
    for (int i = 0; i < 2; ++i) {
        const int s = tid + i * 256;
        const int orow = s >> 3;
        const int oc = (s & 7) * 8;
        __nv_bfloat16 hv[8], lv[8];
#pragma unroll
        for (int j = 0; j < 8; ++j) {
            const float v = t[oc + j][orow];
            hv[j] = __float2bfloat16(v);
            lv[j] = __float2bfloat16(v - __bfloat162float(hv[j]));
        }
        const size_t o = (size_t)(c0 + orow) * R + r0 + oc;
        *reinterpret_cast<uint4*>(ht + o) = *reinterpret_cast<const uint4*>(hv);
        *reinterpret_cast<uint4*>(lt + o) = *reinterpret_cast<const uint4*>(lv);
    }
}

// ------------------ fused softmax + sparse-gather output --------------------
#define SIG_CAP 512
__global__ __launch_bounds__(256)
void softmax_out_kernel(float* __restrict__ attn, const float* __restrict__ V,
                        float* __restrict__ out)
{
    const int rowg = blockIdx.x;           // 0 .. (slabBatches*N)-1
    const int bz   = rowg >> 11;           // / N_
    float* p = attn + (size_t)rowg * N_;
    const float* Vb = V + (size_t)bz * N_ * H_;
    const int tid = threadIdx.x;

    __shared__ float red[256];
    __shared__ int   idxs[SIG_CAP];
    __shared__ float wts[SIG_CAP];
    __shared__ int   cnt;
    if (tid == 0) cnt = 0;

    float x[8];
#pragma unroll
    for (int j = 0; j < 8; ++j) x[j] = p[tid + j * 256];

    float lmax = x[0];
#pragma unroll
    for (int j = 1; j < 8; ++j) lmax = fmaxf(lmax, x[j]);
    red[tid] = lmax;
    __syncthreads();
#pragma unroll
    for (int s = 128; s > 0; s >>= 1) {
        if (tid < s) red[tid] = fmaxf(red[tid], red[tid + s]);
        __syncthreads();
    }
    const float rmax = red[0];
    __syncthreads();

    float lsum = 0.f;
#pragma unroll
    for (int j = 0; j < 8; ++j) {
        x[j] = __expf(x[j] - rmax);
        lsum += x[j];
    }
    red[tid] = lsum;
    __syncthreads();
#pragma unroll
    for (int s = 128; s > 0; s >>= 1) {
        if (tid < s) red[tid] += red[tid + s];
        __syncthreads();
    }
    const float inv = 1.0f / red[0];
    __syncthreads();

#pragma unroll
    for (int j = 0; j < 8; ++j) {
        const float w = x[j] * inv;
        x[j] = w;
        p[tid + j * 256] = w;
        if (w > 1e-9f) {
            const int s = atomicAdd(&cnt, 1);
            if (s < SIG_CAP) { idxs[s] = tid + j * 256; wts[s] = w; }
        }
    }
    __syncthreads();

    const int n = cnt;
    if (tid == 0 && n > 1 && n <= SIG_CAP) {
        for (int i = 1; i < n; ++i) {
            const int ki = idxs[i]; const float kw = wts[i];
            int j = i - 1;
            while (j >= 0 && idxs[j] > ki) {
                idxs[j + 1] = idxs[j]; wts[j + 1] = wts[j]; --j;
            }
            idxs[j + 1] = ki; wts[j + 1] = kw;
        }
    }
    __syncthreads();

    const int col = tid * 4;
    float4 acc = make_float4(0.f, 0.f, 0.f, 0.f);
    if (n <= SIG_CAP) {
        for (int s = 0; s < n; ++s) {
            const float w = wts[s];
            const float4 v = *reinterpret_cast<const float4*>(
                Vb + (size_t)idxs[s] * H_ + col);
            acc.x += w * v.x; acc.y += w * v.y;
            acc.z += w * v.z; acc.w += w * v.w;
        }
    } else {
        for (int i = 0; i < N_; ++i) {
            const float w = p[i];
            if (w > 0.f) {
                const float4 v = *reinterpret_cast<const float4*>(
                    Vb + (size_t)i * H_ + col);
                acc.x += w * v.x; acc.y += w * v.y;
                acc.z += w * v.z; acc.w += w * v.w;
            }
        }
    }
    *reinterpret_cast<float4*>(out + (size_t)rowg * H_ + col) = acc;
}

// --------------------------------- launch -----------------------------------
extern "C" void kernel_launch(void* const* d_in, const int* in_sizes, int n_in,
                              void* d_out, int out_size)
{
    const float* query = (const float*)d_in[0];   // (B, N, H)
    const float* value = (const float*)d_in[1];   // (B, N, H)
    const int*   mask  = (const int*)d_in[2];     // (B, N, N)
    const float* W     = (const float*)d_in[3];   // (H, H)

    float* out  = (float*)d_out;                   // (B, N, H)
    float* attn = out + (size_t)B_ * N_ * H_;      // (B, N, N)

    __nv_bfloat16 *Qh, *Ql, *Wth, *Wtl, *Vh, *Vl, *Ih, *Il;
    cudaGetSymbolAddress((void**)&Qh,  g_Qh);
    cudaGetSymbolAddress((void**)&Ql,  g_Ql);
    cudaGetSymbolAddress((void**)&Wth, g_Wth);
    cudaGetSymbolAddress((void**)&Wtl, g_Wtl);
    cudaGetSymbolAddress((void**)&Vh,  g_Vh);
    cudaGetSymbolAddress((void**)&Vl,  g_Vl);
    cudaGetSymbolAddress((void**)&Ih,  g_Ih);
    cudaGetSymbolAddress((void**)&Il,  g_Il);

    cudaFuncSetAttribute(gemm_sp<0>, cudaFuncAttributeMaxDynamicSharedMemorySize, SMEM_BYTES);
    cudaFuncSetAttribute(gemm_sp<1>, cudaFuncAttributeMaxDynamicSharedMemorySize, SMEM_BYTES);

    // one side stream + two re-recorded events (proven allocation footprint)
    static cudaStream_t s2 = nullptr;
    static cudaEvent_t evA = nullptr, evB = nullptr;
    if (!s2) {
        cudaStreamCreateWithFlags(&s2, cudaStreamNonBlocking);
        cudaEventCreateWithFlags(&evA, cudaEventDisableTiming);
        cudaEventCreateWithFlags(&evB, cudaEventDisableTiming);
    }

    const size_t nQ  = (size_t)B_ * N_ * H_;
    const size_t bQ  = (size_t)N_ * H_;       // per-batch Q/V/interm elems
    const size_t bAt = (size_t)N_ * N_;       // per-batch attn/mask elems
    const int    HB  = B_ / 2;                // batches per chain
    const size_t oQ  = (size_t)HB * bQ;       // chain-B offsets
    const size_t oAt = (size_t)HB * bAt;
    const size_t hQ  = oQ;                    // elems per Q half
    const unsigned halfGrid = (unsigned)(hQ / 4 / 256);

    // 1) fork
    cudaEventRecord(evA, 0);
    cudaStreamWaitEvent(s2, evA, 0);

    // 2) s0: W transpose first; evA (re-record) = "W ready"
    tsplit_kernel<<<dim3(H_ / 64, H_ / 64), 256>>>(W, Wth, Wtl, H_, H_);
    cudaEventRecord(evA, 0);

    // 3) s2: Q[4-7] split, then full V split; evB = "V ready"
    split_kernel<<<halfGrid, 256, 0, s2>>>(query + oQ, Qh + oQ, Ql + oQ, hQ);
    split_kernel<<<(unsigned)(nQ / 4 / 256), 256, 0, s2>>>(value, Vh, Vl, nQ);
    cudaEventRecord(evB, s2);

    // 4) s0 chain A: Q[0-3] split; GEMM1(A)
    split_kernel<<<halfGrid, 256>>>(query, Qh, Ql, hQ);
    gemm_sp<0><<<dim3(H_ / 128, (HB * N_) / 128, 1), 256, SMEM_BYTES>>>(
        Qh, Ql, Wth, Wtl, nullptr, Ih, Il, nullptr,
        H_, H_, 0, 0, 0, 0);
    cudaStreamWaitEvent(0, evB, 0);   // V ready (binds to record in step 3)

    // 5) s2 chain B: wait W; GEMM1(B); GEMM2(B)
    cudaStreamWaitEvent(s2, evA, 0);  // W ready (binds to record in step 2)
    gemm_sp<0><<<dim3(H_ / 128, (HB * N_) / 128, 1), 256, SMEM_BYTES, s2>>>(
        Qh + oQ, Ql + oQ, Wth, Wtl, nullptr, Ih + oQ, Il + oQ, nullptr,
        H_, H_, 0, 0, 0, 0);
    gemm_sp<1><<<dim3(N_ / 128, N_ / 128, HB), 256, SMEM_BYTES, s2>>>(
        Ih + oQ, Il + oQ, Vh + oQ, Vl + oQ, attn + oAt, nullptr, nullptr,
        mask + oAt, H_, N_, bQ, bQ, bAt, bAt);

    // 6) s0 chain A tail: GEMM2(A); softmax(A)
    gemm_sp<1><<<dim3(N_ / 128, N_ / 128, HB), 256, SMEM_BYTES>>>(
        Ih, Il, Vh, Vl, attn, nullptr, nullptr, mask,
        H_, N_, bQ, bQ, bAt, bAt);
    softmax_out_kernel<<<HB * N_, 256>>>(attn, value, out);

    // 7) tail split: chain-B softmax runs half on each stream.
    //    evA (re-record) = "G2b done" -- all prior evA waits already enqueued.
    cudaEventRecord(evA, s2);
    cudaStreamWaitEvent(0, evA, 0);
    const int HHB = HB / 2;
    softmax_out_kernel<<<HHB * N_, 256>>>(
        attn + oAt, value + oQ, out + oQ);
    softmax_out_kernel<<<HHB * N_, 256, 0, s2>>>(
        attn + oAt + (size_t)HHB * bAt,
        value + oQ + (size_t)HHB * bQ,
        out + oQ + (size_t)HHB * bQ);

    // 8) join: evB (re-record) = "chain B stream done"
    cudaEventRecord(evB, s2);
    cudaStreamWaitEvent(0, evB, 0);
}

// round 16
// speedup vs baseline: 1.6310x; 1.3881x over previous
#include <cuda_runtime.h>
#include <cuda_bf16.h>
#include <cstdint>

// ---------------------------------------------------------------------------
// BilinearAttention:
//   GEMM1 (split-bf16, 3-pass): interm = Q @ W -> fp32 + bf16(hi)
//   GEMM2 (single-pass bf16):   approx logits = mask/relu(interm_h @ Vh^T)
//   softmax+refine: candidates (approx > max-31) recomputed EXACTLY in fp32
//                   from interm_f32 and V; weights exact where it matters.
//   out = sparse gather of V rows by exact weights.
// Two-chain launcher (R15-proven). Output: [ out (B*N*H) | attn (B*N*N) ]
// ---------------------------------------------------------------------------

#define B_   8
#define N_   2048
#define H_   1024

// ------------------------- scratch (no allocations) -------------------------
__device__ __nv_bfloat16 g_Qh[(size_t)B_ * N_ * H_];
__device__ __nv_bfloat16 g_Ql[(size_t)B_ * N_ * H_];
__device__ __nv_bfloat16 g_Wth[(size_t)H_ * H_];
__device__ __nv_bfloat16 g_Wtl[(size_t)H_ * H_];
__device__ __nv_bfloat16 g_Vh[(size_t)B_ * N_ * H_];
__device__ __nv_bfloat16 g_Ih[(size_t)B_ * N_ * H_];
__device__ float         g_If[(size_t)B_ * N_ * H_];

// ----------------------------- PTX primitives -------------------------------
__device__ __forceinline__ uint32_t smem_u32(const void* p) {
    uint32_t a;
    asm("{ .reg .u64 t; cvta.to.shared.u64 t, %1; cvt.u32.u64 %0, t; }"
        : "=r"(a) : "l"(p));
    return a;
}
__device__ __forceinline__ void cp16(uint32_t dst, const void* src) {
    asm volatile("cp.async.cg.shared.global [%0], [%1], 16;" :: "r"(dst), "l"(src));
}
__device__ __forceinline__ void cp_commit() {
    asm volatile("cp.async.commit_group;" ::: "memory");
}
template<int Nn>
__device__ __forceinline__ void cp_wait() {
    asm volatile("cp.async.wait_group %0;" :: "n"(Nn) : "memory");
}
__device__ __forceinline__ void ldm_x4(uint32_t& r0, uint32_t& r1, uint32_t& r2,
                                       uint32_t& r3, uint32_t addr) {
    asm volatile("ldmatrix.sync.aligned.m8n8.x4.shared.b16 {%0,%1,%2,%3}, [%4];"
                 : "=r"(r0), "=r"(r1), "=r"(r2), "=r"(r3) : "r"(addr));
}
__device__ __forceinline__ void mma16816(float* c, const uint32_t* a, const uint32_t* b) {
    asm volatile(
        "mma.sync.aligned.m16n8k16.row.col.f32.bf16.bf16.f32 "
        "{%0,%1,%2,%3}, {%4,%5,%6,%7}, {%8,%9}, {%0,%1,%2,%3};"
        : "+f"(c[0]), "+f"(c[1]), "+f"(c[2]), "+f"(c[3])
        : "r"(a[0]), "r"(a[1]), "r"(a[2]), "r"(a[3]), "r"(b[0]), "r"(b[1]));
}
__device__ __forceinline__ void stcs_f2(float* p, float2 v) {
    asm volatile("st.global.cs.v2.f32 [%0], {%1, %2};" :: "l"(p), "f"(v.x), "f"(v.y));
}

// ------------------- GEMM1: split-bf16 (3-pass), fp32+hi out -----------------
#define A_T   8192
#define STAGE (4 * A_T)
#define SMEM3 (3 * STAGE)

__global__ __launch_bounds__(256, 2)
void gemm_split(const __nv_bfloat16* __restrict__ Ah, const __nv_bfloat16* __restrict__ Al,
                const __nv_bfloat16* __restrict__ Bh, const __nv_bfloat16* __restrict__ Bl,
                float* __restrict__ Cf, __nv_bfloat16* __restrict__ Ch,
                int K, int ldc)
{
    extern __shared__ __align__(1024) char smem[];
    const uint32_t sbase = smem_u32(smem);
    const int tid  = threadIdx.x;
    const int wid  = tid >> 5;
    const int lane = tid & 31;
    const int bm = blockIdx.y * 128;
    const int bn = blockIdx.x * 128;

    const int warpM = wid >> 1;
    const int warpN = wid & 1;
    const int nc = K >> 5;

    float acc[2][8][4];
#pragma unroll
    for (int i = 0; i < 2; i++)
#pragma unroll
        for (int j = 0; j < 8; j++)
#pragma unroll
            for (int q = 0; q < 4; q++) acc[i][j][q] = 0.f;

    auto load_chunk = [&](int c) {
        const int kk = c << 5;
        const uint32_t st = sbase + (uint32_t)(c % 3) * STAGE;
#pragma unroll
        for (int i = 0; i < 2; ++i) {
            const int s = tid + i * 256;
            const int row = s >> 2, col = s & 3;
            const uint32_t off =
                (uint32_t)row * 64 + ((uint32_t)(col ^ ((row >> 1) & 3)) << 4);
            const size_t ga = (size_t)(bm + row) * K + kk + col * 8;
            const size_t gb = (size_t)(bn + row) * K + kk + col * 8;
            cp16(st + off, Ah + ga);
            cp16(st + A_T + off, Al + ga);
            cp16(st + 2 * A_T + off, Bh + gb);
            cp16(st + 3 * A_T + off, Bl + gb);
        }
        cp_commit();
    };

    const uint32_t aRow = (uint32_t)(warpM * 32 + (lane & 15));
    const uint32_t aKhi = (uint32_t)(lane >> 4);
    const uint32_t bRow = (uint32_t)(warpN * 64 + ((lane & 16) >> 1) + (lane & 7));
    const uint32_t bKhi = (uint32_t)((lane >> 3) & 1);

    auto compute_chunk = [&](int buf) {
        const uint32_t st  = sbase + (uint32_t)buf * STAGE;
        const uint32_t sAh = st;
        const uint32_t sAl = st + A_T;
        const uint32_t sBh = st + 2 * A_T;
        const uint32_t sBl = st + 3 * A_T;
#pragma unroll
        for (int ks = 0; ks < 2; ++ks) {
            uint32_t ah[2][4], al[2][4], bh[8][2], bl[8][2];
#pragma unroll
            for (int mt = 0; mt < 2; ++mt) {
                const uint32_t row = aRow + mt * 16;
                const uint32_t seg = ((uint32_t)(ks * 2) + aKhi) ^ ((row >> 1) & 3);
                const uint32_t off = row * 64 + (seg << 4);
                ldm_x4(ah[mt][0], ah[mt][1], ah[mt][2], ah[mt][3], sAh + off);
                ldm_x4(al[mt][0], al[mt][1], al[mt][2], al[mt][3], sAl + off);
            }
#pragma unroll
            for (int nb = 0; nb < 4; ++nb) {
                const uint32_t row = bRow + nb * 16;
                const uint32_t seg = ((uint32_t)(ks * 2) + bKhi) ^ ((row >> 1) & 3);
                ldm_x4(bh[nb * 2][0], bh[nb * 2][1], bh[nb * 2 + 1][0], bh[nb * 2 + 1][1],
                       sBh + row * 64 + (seg << 4));
            }
#pragma unroll
            for (int nb = 0; nb < 4; ++nb) {
                const uint32_t row = bRow + nb * 16;
                const uint32_t seg = ((uint32_t)(ks * 2) + bKhi) ^ ((row >> 1) & 3);
                ldm_x4(bl[nb * 2][0], bl[nb * 2][1], bl[nb * 2 + 1][0], bl[nb * 2 + 1][1],
                       sBl + row * 64 + (seg << 4));
            }
#pragma unroll
            for (int mt = 0; mt < 2; ++mt)
#pragma unroll
                for (int nt = 0; nt < 8; ++nt)
                    mma16816(acc[mt][nt], ah[mt], bh[nt]);
#pragma unroll
            for (int mt = 0; mt < 2; ++mt)
#pragma unroll
                for (int nt = 0; nt < 8; ++nt)
                    mma16816(acc[mt][nt], al[mt], bh[nt]);
#pragma unroll
            for (int mt = 0; mt < 2; ++mt)
#pragma unroll
                for (int nt = 0; nt < 8; ++nt)
                    mma16816(acc[mt][nt], ah[mt], bl[nt]);
        }
    };

    load_chunk(0);
    load_chunk(1);
    for (int c = 0; c < nc; ++c) {
        if (c + 1 < nc) cp_wait<1>(); else cp_wait<0>();
        __syncthreads();
        if (c + 2 < nc) load_chunk(c + 2);
        compute_chunk(c % 3);
    }

    const int rBase = bm + warpM * 32 + (lane >> 2);
    const int cBase = bn + warpN * 64 + (lane & 3) * 2;
#pragma unroll
    for (int mt = 0; mt < 2; ++mt)
#pragma unroll
        for (int half = 0; half < 2; ++half) {
            const int row = rBase + mt * 16 + half * 8;
#pragma unroll
            for (int nt = 0; nt < 8; ++nt) {
                const int col = cBase + nt * 8;
                const float v0 = acc[mt][nt][half * 2 + 0];
                const float v1 = acc[mt][nt][half * 2 + 1];
                float2 f; f.x = v0; f.y = v1;
                *reinterpret_cast<float2*>(Cf + (size_t)row * ldc + col) = f;
                __nv_bfloat16 hv[2];
                hv[0] = __float2bfloat16(v0);
                hv[1] = __float2bfloat16(v1);
                *reinterpret_cast<uint32_t*>(Ch + (size_t)row * ldc + col) =
                    *reinterpret_cast<const uint32_t*>(hv);
            }
        }
}

// ------------------- GEMM2: single-pass bf16, mask+relu ---------------------
#define STAGE1 (2 * A_T)
#define SMEM1  (3 * STAGE1)

__global__ __launch_bounds__(256, 2)
void gemm_1p(const __nv_bfloat16* __restrict__ Ah, const __nv_bfloat16* __restrict__ Bh,
             float* __restrict__ Cf, const int* __restrict__ Mask,
             int K, int ldc,
             size_t sA, size_t sB, size_t sC, size_t sM)
{
    extern __shared__ __align__(1024) char smem[];
    const uint32_t sbase = smem_u32(smem);
    const int tid  = threadIdx.x;
    const int wid  = tid >> 5;
    const int lane = tid & 31;
    const int bm = blockIdx.y * 128;
    const int bn = blockIdx.x * 128;
    const int bz = blockIdx.z;

    Ah += (size_t)bz * sA;
    Bh += (size_t)bz * sB;

    const int warpM = wid >> 1;
    const int warpN = wid & 1;
    const int nc = K >> 5;

    float acc[2][8][4];
#pragma unroll
    for (int i = 0; i < 2; i++)
#pragma unroll
        for (int j = 0; j < 8; j++)
#pragma unroll
            for (int q = 0; q < 4; q++) acc[i][j][q] = 0.f;

    auto load_chunk = [&](int c) {
        const int kk = c << 5;
        const uint32_t st = sbase + (uint32_t)(c % 3) * STAGE1;
#pragma unroll
        for (int i = 0; i < 2; ++i) {
            const int s = tid + i * 256;
            const int row = s >> 2, col = s & 3;
            const uint32_t off =
                (uint32_t)row * 64 + ((uint32_t)(col ^ ((row >> 1) & 3)) << 4);
            cp16(st + off, Ah + (size_t)(bm + row) * K + kk + col * 8);
            cp16(st + A_T + off, Bh + (size_t)(bn + row) * K + kk + col * 8);
        }
        cp_commit();
    };

    const uint32_t aRow = (uint32_t)(warpM * 32 + (lane & 15));
    const uint32_t aKhi = (uint32_t)(lane >> 4);
    const uint32_t bRow = (uint32_t)(warpN * 64 + ((lane & 16) >> 1) + (lane & 7));
    const uint32_t bKhi = (uint32_t)((lane >> 3) & 1);

    auto compute_chunk = [&](int buf) {
        const uint32_t sAh = sbase + (uint32_t)buf * STAGE1;
        const uint32_t sBh = sAh + A_T;
#pragma unroll
        for (int ks = 0; ks < 2; ++ks) {
            uint32_t a[2][4], b[8][2];
#pragma unroll
            for (int mt = 0; mt < 2; ++mt) {
                const uint32_t row = aRow + mt * 16;
                const uint32_t seg = ((uint32_t)(ks * 2) + aKhi) ^ ((row >> 1) & 3);
                ldm_x4(a[mt][0], a[mt][1], a[mt][2], a[mt][3],
                       sAh + row * 64 + (seg << 4));
            }
#pragma unroll
            for (int nb = 0; nb < 4; ++nb) {
                const uint32_t row = bRow + nb * 16;
                const uint32_t seg = ((uint32_t)(ks * 2) + bKhi) ^ ((row >> 1) & 3);
                ldm_x4(b[nb * 2][0], b[nb * 2][1], b[nb * 2 + 1][0], b[nb * 2 + 1][1],
                       sBh + row * 64 + (seg << 4));
            }
#pragma unroll
            for (int mt = 0; mt < 2; ++mt)
#pragma unroll
                for (int nt = 0; nt < 8; ++nt)
                    mma16816(acc[mt][nt], a[mt], b[nt]);
        }
    };

    load_chunk(0);
    load_chunk(1);
    for (int c = 0; c < nc; ++c) {
        if (c + 1 < nc) cp_wait<1>(); else cp_wait<0>();
        __syncthreads();
        if (c + 2 < nc) load_chunk(c + 2);
        compute_chunk(c % 3);
    }

    const int rBase = bm + warpM * 32 + (lane >> 2);
    const int cBase = bn + warpN * 64 + (lane & 3) * 2;
#pragma unroll
    for (int mt = 0; mt < 2; ++mt)
#pragma unroll
        for (int half = 0; half < 2; ++half) {
            const int row = rBase + mt * 16 + half * 8;
#pragma unroll
            for (int nt = 0; nt < 8; ++nt) {
                const int col = cBase + nt * 8;
                const int2 m = *reinterpret_cast<const int2*>(
                    Mask + (size_t)bz * sM + (size_t)row * ldc + col);
                float2 v;
                v.x = m.x > 0 ? fmaxf(acc[mt][nt][half * 2 + 0], 0.f) : -1e9f;
                v.y = m.y > 0 ? fmaxf(acc[mt][nt][half * 2 + 1], 0.f) : -1e9f;
                stcs_f2(Cf + (size_t)bz * sC + (size_t)row * ldc + col, v);
            }
        }
}

// --------------------------- conversion kernels -----------------------------
template<bool LO>
__global__ __launch_bounds__(256)
void split_kernel(const float* __restrict__ x, __nv_bfloat16* __restrict__ h,
                  __nv_bfloat16* __restrict__ l, size_t n)
{
    const size_t i = ((size_t)blockIdx.x * blockDim.x + threadIdx.x) * 4;
    if (i >= n) return;
    const float4 v = *reinterpret_cast<const float4*>(x + i);
    __nv_bfloat16 hv[4], lv[4];
    const float vv[4] = {v.x, v.y, v.z, v.w};
#pragma unroll
    for (int j = 0; j < 4; ++j) {
        hv[j] = __float2bfloat16(vv[j]);
        if (LO) lv[j] = __float2bfloat16(vv[j] - __bfloat162float(hv[j]));
    }
    *reinterpret_cast<uint2*>(h + i) = *reinterpret_cast<const uint2*>(hv);
    if (LO) *reinterpret_cast<uint2*>(l + i) = *reinterpret_cast<const uint2*>(lv);
}

__global__ __launch_bounds__(256)
void tsplit_kernel(const float* __restrict__ x,
                   __nv_bfloat16* __restrict__ ht, __nv_bfloat16* __restrict__ lt,
                   int R, int C)
{
    __shared__ float t[64][65];
    const int r0 = blockIdx.y * 64, c0 = blockIdx.x * 64;
    const int tid = threadIdx.x;
    const int rr = tid >> 4;
    const int cc = (tid & 15) * 4;
#pragma unroll
    for (int i = 0; i < 4; ++i) {
        const int row = rr + i * 16;
        const float4 v = *reinterpret_cast<const float4*>(
            x + (size_t)(r0 + row) * C + c0 + cc);
        t[row][cc] = v.x; t[row][cc + 1] = v.y;
        t[row][cc + 2] = v.z; t[row][cc + 3] = v.w;
    }
    __syncthreads();
#pragma unroll
    for (int i = 0; i < 2; ++i) {
        const int s = tid + i * 256;
        const int orow = s >> 3;
        const int oc = (s & 7) * 8;
        __nv_bfloat16 hv[8], lv[8];
#pragma unroll
        for (int j = 0; j < 8; ++j) {
            const float v = t[oc + j][orow];
            hv[j] = __float2bfloat16(v);
            lv[j] = __float2bfloat16(v - __bfloat162float(hv[j]));
        }
        const size_t o = (size_t)(c0 + orow) * R + r0 + oc;
        *reinterpret_cast<uint4*>(ht + o) = *reinterpret_cast<const uint4*>(hv);
        *reinterpret_cast<uint4*>(lt + o) = *reinterpret_cast<const uint4*>(lv);
    }
}

// -------------- softmax with exact sparse refinement + gather ---------------
// Approx logits in attn; candidates (approx > max-31) recomputed exactly in
// fp32 from interm_f32 and V. Non-candidates have true weight < 1.4e-11.
#define CAP 64
__global__ __launch_bounds__(256)
void softmax_refine_kernel(float* __restrict__ attn, const float* __restrict__ If,
                           const float* __restrict__ V, float* __restrict__ out)
{
    const int rowg = blockIdx.x;
    const int bz   = rowg >> 11;
    float* p = attn + (size_t)rowg * N_;
    const float* iRow = If + (size_t)rowg * H_;
    const float* Vb = V + (size_t)bz * N_ * H_;
    const int tid = threadIdx.x;
    const int col = tid * 4;

    __shared__ float red[256];
    __shared__ int   idxs[CAP];
    __shared__ float exls[CAP];
    __shared__ float wts[CAP];
    __shared__ int   cnt;
    __shared__ float sh_emax;
    if (tid == 0) cnt = 0;

    float x[8];
#pragma unroll
    for (int j = 0; j < 8; ++j) x[j] = p[tid + j * 256];

    float lmax = x[0];
#pragma unroll
    for (int j = 1; j < 8; ++j) lmax = fmaxf(lmax, x[j]);
    red[tid] = lmax;
    __syncthreads();
#pragma unroll
    for (int s = 128; s > 0; s >>= 1) {
        if (tid < s) red[tid] = fmaxf(red[tid], red[tid + s]);
        __syncthreads();
    }
    const float amax = red[0];
    __syncthreads();

    int sj[8];
#pragma unroll
    for (int j = 0; j < 8; ++j) {
        sj[j] = -1;
        if (x[j] > amax - 31.f) {
            const int s = atomicAdd(&cnt, 1);
            if (s < CAP) { idxs[s] = tid + j * 256; sj[j] = s; }
        }
    }
    __syncthreads();
    const int n = cnt;

    if (n <= CAP) {
        const float4 iv = *reinterpret_cast<const float4*>(iRow + col);
        for (int c = 0; c < n; ++c) {
            const float4 vv = *reinterpret_cast<const float4*>(
                Vb + (size_t)idxs[c] * H_ + col);
            float s = iv.x * vv.x + iv.y * vv.y + iv.z * vv.z + iv.w * vv.w;
#pragma unroll
            for (int o = 16; o > 0; o >>= 1) s += __shfl_xor_sync(~0u, s, o);
            if ((tid & 31) == 0) red[tid >> 5] = s;
            __syncthreads();
            if (tid == 0) {
                float t = 0.f;
#pragma unroll
                for (int w = 0; w < 8; ++w) t += red[w];
                exls[c] = fmaxf(t, 0.f);       // relu; candidates are unmasked
            }
            __syncthreads();
        }
        if (tid == 0) {
            float m = -3.4e38f;
            for (int c = 0; c < n; ++c) m = fmaxf(m, exls[c]);
            sh_emax = m;
        }
        __syncthreads();
        const float emax = sh_emax;

        float e[8];
        float lsum = 0.f;
#pragma unroll
        for (int j = 0; j < 8; ++j) {
            const float v = (sj[j] >= 0) ? exls[sj[j]] : x[j];
            e[j] = __expf(v - emax);
            lsum += e[j];
        }
        red[tid] = lsum;
        __syncthreads();
#pragma unroll
        for (int s = 128; s > 0; s >>= 1) {
            if (tid < s) red[tid] += red[tid + s];
            __syncthreads();
        }
        const float inv = 1.0f / red[0];
        __syncthreads();

#pragma unroll
        for (int j = 0; j < 8; ++j) {
            const float w = e[j] * inv;
            p[tid + j * 256] = w;
            if (sj[j] >= 0) wts[sj[j]] = w;
        }
        __syncthreads();

        if (tid == 0 && n > 1) {
            for (int i = 1; i < n; ++i) {
                const int ki = idxs[i]; const float kw = wts[i];
                int j = i - 1;
                while (j >= 0 && idxs[j] > ki) {
                    idxs[j + 1] = idxs[j]; wts[j + 1] = wts[j]; --j;
                }
                idxs[j + 1] = ki; wts[j + 1] = kw;
            }
        }
        __syncthreads();

        float4 acc = make_float4(0.f, 0.f, 0.f, 0.f);
        for (int c = 0; c < n; ++c) {
            const float w = wts[c];
            if (w > 1e-9f) {
                const float4 vv = *reinterpret_cast<const float4*>(
                    Vb + (size_t)idxs[c] * H_ + col);
                acc.x += w * vv.x; acc.y += w * vv.y;
                acc.z += w * vv.z; acc.w += w * vv.w;
            }
        }
        *reinterpret_cast<float4*>(out + (size_t)rowg * H_ + col) = acc;
    } else {
        // --------- fallback (practically unreachable, fully exact) ----------
        const float4 iv = *reinterpret_cast<const float4*>(iRow + col);
        for (int i = 0; i < N_; ++i) {
            const float apx = p[i];
            float s = 0.f;
            if (apx > -0.5e9f) {
                const float4 vv = *reinterpret_cast<const float4*>(
                    Vb + (size_t)i * H_ + col);
                s = iv.x * vv.x + iv.y * vv.y + iv.z * vv.z + iv.w * vv.w;
            }
#pragma unroll
            for (int o = 16; o > 0; o >>= 1) s += __shfl_xor_sync(~0u, s, o);
            if ((tid & 31) == 0) red[tid >> 5] = s;
            __syncthreads();
            if (tid == 0) {
                float t = 0.f;
#pragma unroll
                for (int w = 0; w < 8; ++w) t += red[w];
                p[i] = (apx > -0.5e9f) ? fmaxf(t, 0.f) : -1e9f;
            }
            __syncthreads();
        }
        float m = -3.4e38f;
        for (int i = tid; i < N_; i += 256) m = fmaxf(m, p[i]);
        red[tid] = m;
        __syncthreads();
#pragma unroll
        for (int s = 128; s > 0; s >>= 1) {
            if (tid < s) red[tid] = fmaxf(red[tid], red[tid + s]);
            __syncthreads();
        }
        const float rmax = red[0];
        __syncthreads();
        float lsum = 0.f;
        for (int i = tid; i < N_; i += 256) {
            const float v = __expf(p[i] - rmax);
            p[i] = v;
            lsum += v;
        }
        red[tid] = lsum;
        __syncthreads();
#pragma unroll
        for (int s = 128; s > 0; s >>= 1) {
            if (tid < s) red[tid] += red[tid + s];
            __syncthreads();
        }
        const float inv = 1.0f / red[0];
        __syncthreads();
        for (int i = tid; i < N_; i += 256) p[i] *= inv;
        __syncthreads();
        float4 acc = make_float4(0.f, 0.f, 0.f, 0.f);
        for (int i = 0; i < N_; ++i) {
            const float w = p[i];
            if (w > 0.f) {
                const float4 vv = *reinterpret_cast<const float4*>(
                    Vb + (size_t)i * H_ + col);
                acc.x += w * vv.x; acc.y += w * vv.y;
                acc.z += w * vv.z; acc.w += w * vv.w;
            }
        }
        *reinterpret_cast<float4*>(out + (size_t)rowg * H_ + col) = acc;
    }
}

// --------------------------------- launch -----------------------------------
extern "C" void kernel_launch(void* const* d_in, const int* in_sizes, int n_in,
                              void* d_out, int out_size)
{
    const float* query = (const float*)d_in[0];   // (B, N, H)
    const float* value = (const float*)d_in[1];   // (B, N, H)
    const int*   mask  = (const int*)d_in[2];     // (B, N, N)
    const float* W     = (const float*)d_in[3];   // (H, H)

    float* out  = (float*)d_out;                   // (B, N, H)
    float* attn = out + (size_t)B_ * N_ * H_;      // (B, N, N)

    __nv_bfloat16 *Qh, *Ql, *Wth, *Wtl, *Vh, *Ih;
    float* If;
    cudaGetSymbolAddress((void**)&Qh,  g_Qh);
    cudaGetSymbolAddress((void**)&Ql,  g_Ql);
    cudaGetSymbolAddress((void**)&Wth, g_Wth);
    cudaGetSymbolAddress((void**)&Wtl, g_Wtl);
    cudaGetSymbolAddress((void**)&Vh,  g_Vh);
    cudaGetSymbolAddress((void**)&Ih,  g_Ih);
    cudaGetSymbolAddress((void**)&If,  g_If);

    cudaFuncSetAttribute(gemm_split, cudaFuncAttributeMaxDynamicSharedMemorySize, SMEM3);
    cudaFuncSetAttribute(gemm_1p,    cudaFuncAttributeMaxDynamicSharedMemorySize, SMEM1);

    static cudaStream_t s2 = nullptr;
    static cudaEvent_t evA = nullptr, evB = nullptr;
    if (!s2) {
        cudaStreamCreateWithFlags(&s2, cudaStreamNonBlocking);
        cudaEventCreateWithFlags(&evA, cudaEventDisableTiming);
        cudaEventCreateWithFlags(&evB, cudaEventDisableTiming);
    }

    const size_t nQ  = (size_t)B_ * N_ * H_;
    const size_t bQ  = (size_t)N_ * H_;
    const size_t bAt = (size_t)N_ * N_;
    const int    HB  = B_ / 2;
    const size_t oQ  = (size_t)HB * bQ;
    const size_t oAt = (size_t)HB * bAt;
    const size_t hQ  = oQ;
    const unsigned halfGrid = (unsigned)(hQ / 4 / 256);

    // 1) fork
    cudaEventRecord(evA, 0);
    cudaStreamWaitEvent(s2, evA, 0);

    // 2) s0: W transpose; evA (re-record) = "W ready"
    tsplit_kernel<<<dim3(H_ / 64, H_ / 64), 256>>>(W, Wth, Wtl, H_, H_);
    cudaEventRecord(evA, 0);

    // 3) s2: Q[4-7] split, then V split (hi only); evB = "V ready"
    split_kernel<true><<<halfGrid, 256, 0, s2>>>(query + oQ, Qh + oQ, Ql + oQ, hQ);
    split_kernel<false><<<(unsigned)(nQ / 4 / 256), 256, 0, s2>>>(value, Vh, nullptr, nQ);
    cudaEventRecord(evB, s2);

    // 4) s0 chain A: Q[0-3] split; GEMM1(A)
    split_kernel<true><<<halfGrid, 256>>>(query, Qh, Ql, hQ);
    gemm_split<<<dim3(H_ / 128, (HB * N_) / 128), 256, SMEM3>>>(
        Qh, Ql, Wth, Wtl, If, Ih, H_, H_);
    cudaStreamWaitEvent(0, evB, 0);   // V ready

    // 5) s2 chain B: wait W; GEMM1(B); GEMM2(B)
    cudaStreamWaitEvent(s2, evA, 0);
    gemm_split<<<dim3(H_ / 128, (HB * N_) / 128), 256, SMEM3, s2>>>(
        Qh + oQ, Ql + oQ, Wth, Wtl, If + oQ, Ih + oQ, H_, H_);
    gemm_1p<<<dim3(N_ / 128, N_ / 128, HB), 256, SMEM1, s2>>>(
        Ih + oQ, Vh + oQ, attn + oAt, mask + oAt,
        H_, N_, bQ, bQ, bAt, bAt);

    // 6) s0 chain A tail: GEMM2(A); softmax(A)
    gemm_1p<<<dim3(N_ / 128, N_ / 128, HB), 256, SMEM1>>>(
        Ih, Vh, attn, mask, H_, N_, bQ, bQ, bAt, bAt);
    softmax_refine_kernel<<<HB * N_, 256>>>(attn, If, value, out);

    // 7) tail split: chain-B softmax half on each stream
    cudaEventRecord(evA, s2);
    cudaStreamWaitEvent(0, evA, 0);
    const int HHB = HB / 2;
    softmax_refine_kernel<<<HHB * N_, 256>>>(
        attn + oAt, If + oQ, value + oQ, out + oQ);
    softmax_refine_kernel<<<HHB * N_, 256, 0, s2>>>(
        attn + oAt + (size_t)HHB * bAt, If + oQ + (size_t)HHB * bQ,
        value + oQ + (size_t)HHB * bQ, out + oQ + (size_t)HHB * bQ);

    // 8) join
    cudaEventRecord(evB, s2);
    cudaStreamWaitEvent(0, evB, 0);
}